// round 10
// baseline (speedup 1.0000x reference)
#include <cuda_runtime.h>
#include <cuda_bf16.h>
#include <cstdint>

// ============================================================================
// FNO — fused FFT formulation.
//   h = relu(mu @ W1 + b1)                       (encoder SGEMM -> g_h scratch)
//   4x: h = relu( ifft(fft([x;h[:253]]) * w_full).real + lw*h )   (warp FFT)
//   out = h @ W2 + b2                            (fused decoder epilogue)
// ============================================================================

#define B_ROWS 262144

// 262144 * 256 floats = 256 MB scratch for encoder output (allowed: __device__ global)
__device__ float g_h[67108864];

static __device__ __forceinline__ float2 cmul(float2 a, float2 b) {
    return make_float2(fmaf(a.x, b.x, -a.y * b.y), fmaf(a.x, b.y, a.y * b.x));
}
static __device__ __forceinline__ float2 cadd(float2 a, float2 b) {
    return make_float2(a.x + b.x, a.y + b.y);
}
static __device__ __forceinline__ float2 csub(float2 a, float2 b) {
    return make_float2(a.x - b.x, a.y - b.y);
}
static __device__ __forceinline__ float2 conjf2(float2 a) {
    return make_float2(a.x, -a.y);
}

// ---------------------------------------------------------------------------
// Encoder: h = relu(mu @ W1 + b1).  mu [B,64], W1 [64,256].
// Block: 64 rows x 256 cols, 256 threads, 8x8 microtile, BK=16.
// ---------------------------------------------------------------------------
__global__ __launch_bounds__(256) void encoder_kernel(
    const float* __restrict__ mu, const float* __restrict__ W1,
    const float* __restrict__ b1)
{
    __shared__ float As[16][68];    // [k][row], padded
    __shared__ float Bs[16][256];   // [k][col]

    const int tid  = threadIdx.x;
    const int row0 = blockIdx.x * 64;
    const int tx   = tid & 31;   // col group (8 cols each)
    const int ty   = tid >> 5;   // row group (8 rows each)

    float acc[8][8];
#pragma unroll
    for (int i = 0; i < 8; i++)
#pragma unroll
        for (int j = 0; j < 8; j++) acc[i][j] = 0.f;

#pragma unroll
    for (int k0 = 0; k0 < 64; k0 += 16) {
        // --- load A tile (64 rows x 16 k), transpose into As[k][row]
        {
            int r  = tid >> 2;            // 0..63
            int kq = (tid & 3) * 4;       // 0,4,8,12
            float4 a4 = *reinterpret_cast<const float4*>(
                mu + (size_t)(row0 + r) * 64 + k0 + kq);
            As[kq + 0][r] = a4.x;
            As[kq + 1][r] = a4.y;
            As[kq + 2][r] = a4.z;
            As[kq + 3][r] = a4.w;
        }
        // --- load B tile (16 k x 256 cols)
#pragma unroll
        for (int q = 0; q < 4; q++) {
            int idx = tid + q * 256;          // 0..1023 float4 slots
            int kk  = idx >> 6;               // /64
            int c4  = (idx & 63) * 4;
            *reinterpret_cast<float4*>(&Bs[kk][c4]) =
                *reinterpret_cast<const float4*>(W1 + (size_t)(k0 + kk) * 256 + c4);
        }
        __syncthreads();

#pragma unroll
        for (int kk = 0; kk < 16; kk++) {
            float a[8], b[8];
#pragma unroll
            for (int i = 0; i < 8; i++) a[i] = As[kk][ty * 8 + i];
            {
                float4 b0 = *reinterpret_cast<const float4*>(&Bs[kk][tx * 8]);
                float4 b1v = *reinterpret_cast<const float4*>(&Bs[kk][tx * 8 + 4]);
                b[0] = b0.x; b[1] = b0.y; b[2] = b0.z; b[3] = b0.w;
                b[4] = b1v.x; b[5] = b1v.y; b[6] = b1v.z; b[7] = b1v.w;
            }
#pragma unroll
            for (int i = 0; i < 8; i++)
#pragma unroll
                for (int j = 0; j < 8; j++) acc[i][j] = fmaf(a[i], b[j], acc[i][j]);
        }
        __syncthreads();
    }

    // epilogue: relu(acc + b1) -> g_h
#pragma unroll
    for (int i = 0; i < 8; i++) {
        int r = row0 + ty * 8 + i;
#pragma unroll
        for (int j = 0; j < 8; j += 4) {
            int c = tx * 8 + j;
            float4 o;
            o.x = fmaxf(acc[i][j + 0] + b1[c + 0], 0.f);
            o.y = fmaxf(acc[i][j + 1] + b1[c + 1], 0.f);
            o.z = fmaxf(acc[i][j + 2] + b1[c + 2], 0.f);
            o.w = fmaxf(acc[i][j + 3] + b1[c + 3], 0.f);
            *reinterpret_cast<float4*>(&g_h[(size_t)r * 256 + c]) = o;
        }
    }
}

// ---------------------------------------------------------------------------
// Fused Fourier layers + decoder. One warp per row; lane l holds indices
// {32j + l : j=0..7}. Forward radix-2 DIF (bit-reversed out), pointwise by
// bit-reversed weights (with 1/256 folded in), inverse radix-2 DIT.
// ---------------------------------------------------------------------------
__global__ __launch_bounds__(256) void fno_fft_kernel(
    const float* __restrict__ xg,  const float* __restrict__ fw,
    const float* __restrict__ lw,  const float* __restrict__ W2,
    const float* __restrict__ b2,  float* __restrict__ out)
{
    __shared__ float2 T[128];        // T[k] = exp(-2*pi*i*k/256)
    __shared__ float  wbr[4][256];   // spectral weights, bit-reversed order, /256
    __shared__ float  lws[4][256];
    __shared__ float  W2s[256];

    const int tid = threadIdx.x;
    if (tid < 128) {
        float s, c;
        sincospif((float)tid / 128.0f, &s, &c);
        T[tid] = make_float2(c, -s);
    }
    for (int i = tid; i < 1024; i += blockDim.x) {
        int l = i >> 8, p = i & 255;
        int m  = __brev((unsigned)p) >> 24;       // bitrev8
        int mm = (m <= 128) ? m : 256 - m;
        wbr[l][p] = fw[l * 129 + mm] * (1.0f / 256.0f);
        lws[l][p] = lw[i];
    }
    if (tid < 256) W2s[tid] = W2[tid];
    __syncthreads();

    const float b2v  = b2[0];
    const int lane   = tid & 31;
    const int warp   = tid >> 5;
    const unsigned FULL = 0xFFFFFFFFu;
    const int warpsTotal = gridDim.x * (blockDim.x >> 5);

    for (int row = blockIdx.x * (blockDim.x >> 5) + warp; row < B_ROWS;
         row += warpsTotal) {

        float h[8];
#pragma unroll
        for (int j = 0; j < 8; j++)
            h[j] = g_h[(size_t)row * 256 + j * 32 + lane];
        const float xv = (lane < 3) ? xg[(size_t)row * 3 + lane] : 0.f;

#pragma unroll
        for (int layer = 0; layer < 4; layer++) {
            // ---- build d = [x0,x1,x2, h0..h252] via lane rotate-by-3 ----
            float sh[8];
#pragma unroll
            for (int j = 0; j < 8; j++)
                sh[j] = __shfl_sync(FULL, h[j], (lane + 29) & 31);
            float2 v[8];
#pragma unroll
            for (int j = 0; j < 8; j++) {
                float d;
                if (lane >= 3) d = sh[j];
                else           d = (j == 0) ? xv : sh[j - 1];
                v[j] = make_float2(d, 0.f);
            }

            // ================= forward DIF =================
            // L=256 (local, pairs j, j+4)
#pragma unroll
            for (int j = 0; j < 4; j++) {
                float2 a = v[j], b = v[j + 4];
                float2 W = T[j * 32 + lane];
                v[j]     = cadd(a, b);
                v[j + 4] = cmul(csub(a, b), W);
            }
            // L=128 (local, pairs (0,2),(1,3),(4,6),(5,7))
#pragma unroll
            for (int p = 0; p < 4; p++) {
                int j = (p < 2) ? p : p + 2;
                float2 a = v[j], b = v[j + 2];
                float2 W = T[((j & 1) * 32 + lane) * 2];
                v[j]     = cadd(a, b);
                v[j + 2] = cmul(csub(a, b), W);
            }
            // L=64 (local, pairs j even)
            {
                float2 W = T[lane * 4];
#pragma unroll
                for (int j = 0; j < 8; j += 2) {
                    float2 a = v[j], b = v[j + 1];
                    v[j]     = cadd(a, b);
                    v[j + 1] = cmul(csub(a, b), W);
                }
            }
            // cross-lane stages s = 16,8,4,2,1
#pragma unroll
            for (int st = 0; st < 5; st++) {
                const int s = 16 >> st;
                float2 W = (s > 1) ? T[(lane & (s - 1)) * (128 / s)]
                                   : make_float2(1.f, 0.f);
                const bool upper = (lane & s) != 0;
#pragma unroll
                for (int j = 0; j < 8; j++) {
                    float2 o;
                    o.x = __shfl_xor_sync(FULL, v[j].x, s);
                    o.y = __shfl_xor_sync(FULL, v[j].y, s);
                    if (!upper) {
                        v[j].x += o.x; v[j].y += o.y;
                    } else {
                        v[j] = cmul(make_float2(o.x - v[j].x, o.y - v[j].y), W);
                    }
                }
            }

            // ---- pointwise multiply (bit-reversed domain) ----
#pragma unroll
            for (int j = 0; j < 8; j++) {
                float w = wbr[layer][j * 32 + lane];
                v[j].x *= w; v[j].y *= w;
            }

            // ================= inverse DIT =================
            // cross-lane stages s = 1,2,4,8,16
#pragma unroll
            for (int st = 0; st < 5; st++) {
                const int s = 1 << st;
                float2 W = (s > 1) ? conjf2(T[(lane & (s - 1)) * (128 / s)])
                                   : make_float2(1.f, 0.f);
                const bool upper = (lane & s) != 0;
#pragma unroll
                for (int j = 0; j < 8; j++) {
                    float2 o;
                    o.x = __shfl_xor_sync(FULL, v[j].x, s);
                    o.y = __shfl_xor_sync(FULL, v[j].y, s);
                    if (!upper) {
                        float2 t2 = cmul(o, W);
                        v[j].x += t2.x; v[j].y += t2.y;
                    } else {
                        float2 t2 = cmul(v[j], W);
                        v[j] = make_float2(o.x - t2.x, o.y - t2.y);
                    }
                }
            }
            // L=64 (local)
            {
                float2 W = conjf2(T[lane * 4]);
#pragma unroll
                for (int j = 0; j < 8; j += 2) {
                    float2 u = v[j];
                    float2 t2 = cmul(v[j + 1], W);
                    v[j]     = cadd(u, t2);
                    v[j + 1] = csub(u, t2);
                }
            }
            // L=128 (local)
#pragma unroll
            for (int p = 0; p < 4; p++) {
                int j = (p < 2) ? p : p + 2;
                float2 W = conjf2(T[((j & 1) * 32 + lane) * 2]);
                float2 u = v[j];
                float2 t2 = cmul(v[j + 2], W);
                v[j]     = cadd(u, t2);
                v[j + 2] = csub(u, t2);
            }
            // L=256 (local)
#pragma unroll
            for (int j = 0; j < 4; j++) {
                float2 W = conjf2(T[j * 32 + lane]);
                float2 u = v[j];
                float2 t2 = cmul(v[j + 4], W);
                v[j]     = cadd(u, t2);
                v[j + 4] = csub(u, t2);
            }

            // ---- residual + relu ----
#pragma unroll
            for (int j = 0; j < 8; j++)
                h[j] = fmaxf(fmaf(lws[layer][j * 32 + lane], h[j], v[j].x), 0.f);
        }

        // ---- decoder: out = h . W2 + b2 ----
        float acc = 0.f;
#pragma unroll
        for (int j = 0; j < 8; j++) acc = fmaf(h[j], W2s[j * 32 + lane], acc);
#pragma unroll
        for (int s = 16; s; s >>= 1) acc += __shfl_xor_sync(FULL, acc, s);
        if (lane == 0) out[row] = acc + b2v;
    }
}

// ---------------------------------------------------------------------------
extern "C" void kernel_launch(void* const* d_in, const int* in_sizes, int n_in,
                              void* d_out, int out_size)
{
    const float* mu = (const float*)d_in[0];   // [262144, 64]
    const float* x  = (const float*)d_in[1];   // [262144, 3]
    const float* W1 = (const float*)d_in[2];   // [64, 256]
    const float* b1 = (const float*)d_in[3];   // [256]
    const float* fw = (const float*)d_in[4];   // [4, 129]
    const float* lw = (const float*)d_in[5];   // [4, 256]
    const float* W2 = (const float*)d_in[6];   // [256, 1]
    const float* b2 = (const float*)d_in[7];   // [1]
    float* out = (float*)d_out;                // [262144, 1]

    encoder_kernel<<<B_ROWS / 64, 256>>>(mu, W1, b1);
    fno_fft_kernel<<<1184, 256>>>(x, fw, lw, W2, b2, out);
}

// round 12
// speedup vs baseline: 1.7158x; 1.7158x over previous
#include <cuda_runtime.h>
#include <cuda_bf16.h>
#include <cstdint>

// ============================================================================
// FNO — fused FFT formulation with exact two-for-one real packing.
//   h = relu(mu @ W1 + b1)                       (encoder SGEMM -> g_h scratch)
//   4x: h = relu( ifft(fft([x;h[:253]]) * w_full).real + lw*h )
//       -> two rows packed as real+imag of ONE complex 256-pt FFT (w is real,
//          so filtering commutes with the packing; no unpack needed).
//   out = h @ W2 + b2                            (fused decoder epilogue)
// ============================================================================

#define B_ROWS 262144

// 262144 * 256 floats = 256 MB scratch for encoder output
__device__ float g_h[67108864];

static __device__ __forceinline__ float2 cmul(float2 a, float2 b) {
    return make_float2(fmaf(a.x, b.x, -a.y * b.y), fmaf(a.x, b.y, a.y * b.x));
}
static __device__ __forceinline__ float2 cadd(float2 a, float2 b) {
    return make_float2(a.x + b.x, a.y + b.y);
}
static __device__ __forceinline__ float2 csub(float2 a, float2 b) {
    return make_float2(a.x - b.x, a.y - b.y);
}
static __device__ __forceinline__ float2 conjf2(float2 a) {
    return make_float2(a.x, -a.y);
}

// ---------------------------------------------------------------------------
// Encoder: h = relu(mu @ W1 + b1).  mu [B,64], W1 [64,256].
// ---------------------------------------------------------------------------
__global__ __launch_bounds__(256) void encoder_kernel(
    const float* __restrict__ mu, const float* __restrict__ W1,
    const float* __restrict__ b1)
{
    __shared__ float As[16][68];
    __shared__ float Bs[16][256];

    const int tid  = threadIdx.x;
    const int row0 = blockIdx.x * 64;
    const int tx   = tid & 31;
    const int ty   = tid >> 5;

    float acc[8][8];
#pragma unroll
    for (int i = 0; i < 8; i++)
#pragma unroll
        for (int j = 0; j < 8; j++) acc[i][j] = 0.f;

#pragma unroll
    for (int k0 = 0; k0 < 64; k0 += 16) {
        {
            int r  = tid >> 2;
            int kq = (tid & 3) * 4;
            float4 a4 = *reinterpret_cast<const float4*>(
                mu + (size_t)(row0 + r) * 64 + k0 + kq);
            As[kq + 0][r] = a4.x;
            As[kq + 1][r] = a4.y;
            As[kq + 2][r] = a4.z;
            As[kq + 3][r] = a4.w;
        }
#pragma unroll
        for (int q = 0; q < 4; q++) {
            int idx = tid + q * 256;
            int kk  = idx >> 6;
            int c4  = (idx & 63) * 4;
            *reinterpret_cast<float4*>(&Bs[kk][c4]) =
                *reinterpret_cast<const float4*>(W1 + (size_t)(k0 + kk) * 256 + c4);
        }
        __syncthreads();

#pragma unroll
        for (int kk = 0; kk < 16; kk++) {
            float a[8], b[8];
#pragma unroll
            for (int i = 0; i < 8; i++) a[i] = As[kk][ty * 8 + i];
            {
                float4 b0 = *reinterpret_cast<const float4*>(&Bs[kk][tx * 8]);
                float4 b1v = *reinterpret_cast<const float4*>(&Bs[kk][tx * 8 + 4]);
                b[0] = b0.x; b[1] = b0.y; b[2] = b0.z; b[3] = b0.w;
                b[4] = b1v.x; b[5] = b1v.y; b[6] = b1v.z; b[7] = b1v.w;
            }
#pragma unroll
            for (int i = 0; i < 8; i++)
#pragma unroll
                for (int j = 0; j < 8; j++) acc[i][j] = fmaf(a[i], b[j], acc[i][j]);
        }
        __syncthreads();
    }

#pragma unroll
    for (int i = 0; i < 8; i++) {
        int r = row0 + ty * 8 + i;
#pragma unroll
        for (int j = 0; j < 8; j += 4) {
            int c = tx * 8 + j;
            float4 o;
            o.x = fmaxf(acc[i][j + 0] + b1[c + 0], 0.f);
            o.y = fmaxf(acc[i][j + 1] + b1[c + 1], 0.f);
            o.z = fmaxf(acc[i][j + 2] + b1[c + 2], 0.f);
            o.w = fmaxf(acc[i][j + 3] + b1[c + 3], 0.f);
            *reinterpret_cast<float4*>(&g_h[(size_t)r * 256 + c]) = o;
        }
    }
}

// ---------------------------------------------------------------------------
// Fused Fourier layers + decoder. One warp per PAIR of rows (real+imag pack).
// Lane l holds indices {32j + l : j=0..7}. Forward radix-2 DIF (bit-reversed
// out), pointwise by real bit-reversed weights (1/256 folded), inverse DIT.
// ---------------------------------------------------------------------------
__global__ __launch_bounds__(256) void fno_fft_kernel(
    const float* __restrict__ xg,  const float* __restrict__ fw,
    const float* __restrict__ lw,  const float* __restrict__ W2,
    const float* __restrict__ b2,  float* __restrict__ out)
{
    __shared__ float2 T[128];        // T[k] = exp(-2*pi*i*k/256)
    __shared__ float  wbr[4][256];   // spectral weights, bit-reversed, /256
    __shared__ float  lws[4][256];
    __shared__ float  W2s[256];

    const int tid = threadIdx.x;
    if (tid < 128) {
        float s, c;
        sincospif((float)tid / 128.0f, &s, &c);
        T[tid] = make_float2(c, -s);
    }
    for (int i = tid; i < 1024; i += blockDim.x) {
        int l = i >> 8, p = i & 255;
        int m  = __brev((unsigned)p) >> 24;       // bitrev8
        int mm = (m <= 128) ? m : 256 - m;
        wbr[l][p] = fw[l * 129 + mm] * (1.0f / 256.0f);
        lws[l][p] = lw[i];
    }
    if (tid < 256) W2s[tid] = W2[tid];
    __syncthreads();

    const float b2v  = b2[0];
    const int lane   = tid & 31;
    const int warp   = tid >> 5;
    const unsigned FULL = 0xFFFFFFFFu;
    const int warpsTotal = gridDim.x * (blockDim.x >> 5);
    const int NPAIRS = B_ROWS / 2;

    for (int pair = blockIdx.x * (blockDim.x >> 5) + warp; pair < NPAIRS;
         pair += warpsTotal) {

        const int row0 = pair * 2;
        const int row1 = row0 + 1;

        float h0[8], h1[8];
#pragma unroll
        for (int j = 0; j < 8; j++) {
            h0[j] = g_h[(size_t)row0 * 256 + j * 32 + lane];
            h1[j] = g_h[(size_t)row1 * 256 + j * 32 + lane];
        }
        const float xv0 = (lane < 3) ? xg[(size_t)row0 * 3 + lane] : 0.f;
        const float xv1 = (lane < 3) ? xg[(size_t)row1 * 3 + lane] : 0.f;

#pragma unroll
        for (int layer = 0; layer < 4; layer++) {
            // ---- build d = [x0,x1,x2, h0..h252] for both rows (rotate by 3)
            float2 v[8];
            {
                float s0[8], s1[8];
#pragma unroll
                for (int j = 0; j < 8; j++) {
                    s0[j] = __shfl_sync(FULL, h0[j], (lane + 29) & 31);
                    s1[j] = __shfl_sync(FULL, h1[j], (lane + 29) & 31);
                }
#pragma unroll
                for (int j = 0; j < 8; j++) {
                    float d0, d1;
                    if (lane >= 3) { d0 = s0[j];             d1 = s1[j]; }
                    else           { d0 = (j == 0) ? xv0 : s0[j - 1];
                                     d1 = (j == 0) ? xv1 : s1[j - 1]; }
                    v[j] = make_float2(d0, d1);   // row0 -> real, row1 -> imag
                }
            }

            // ================= forward DIF =================
#pragma unroll
            for (int j = 0; j < 4; j++) {   // L=256 (local)
                float2 a = v[j], b = v[j + 4];
                float2 W = T[j * 32 + lane];
                v[j]     = cadd(a, b);
                v[j + 4] = cmul(csub(a, b), W);
            }
#pragma unroll
            for (int p = 0; p < 4; p++) {   // L=128 (local)
                int j = (p < 2) ? p : p + 2;
                float2 a = v[j], b = v[j + 2];
                float2 W = T[((j & 1) * 32 + lane) * 2];
                v[j]     = cadd(a, b);
                v[j + 2] = cmul(csub(a, b), W);
            }
            {                               // L=64 (local)
                float2 W = T[lane * 4];
#pragma unroll
                for (int j = 0; j < 8; j += 2) {
                    float2 a = v[j], b = v[j + 1];
                    v[j]     = cadd(a, b);
                    v[j + 1] = cmul(csub(a, b), W);
                }
            }
#pragma unroll
            for (int st = 0; st < 5; st++) {   // cross-lane s = 16..1
                const int s = 16 >> st;
                float2 W = (s > 1) ? T[(lane & (s - 1)) * (128 / s)]
                                   : make_float2(1.f, 0.f);
                const bool upper = (lane & s) != 0;
#pragma unroll
                for (int j = 0; j < 8; j++) {
                    float2 o;
                    o.x = __shfl_xor_sync(FULL, v[j].x, s);
                    o.y = __shfl_xor_sync(FULL, v[j].y, s);
                    if (!upper) {
                        v[j].x += o.x; v[j].y += o.y;
                    } else {
                        v[j] = cmul(make_float2(o.x - v[j].x, o.y - v[j].y), W);
                    }
                }
            }

            // ---- pointwise multiply (bitrev domain, real weight serves both
            //      packed rows simultaneously) ----
#pragma unroll
            for (int j = 0; j < 8; j++) {
                float w = wbr[layer][j * 32 + lane];
                v[j].x *= w; v[j].y *= w;
            }

            // ================= inverse DIT =================
#pragma unroll
            for (int st = 0; st < 5; st++) {   // cross-lane s = 1..16
                const int s = 1 << st;
                float2 W = (s > 1) ? conjf2(T[(lane & (s - 1)) * (128 / s)])
                                   : make_float2(1.f, 0.f);
                const bool upper = (lane & s) != 0;
#pragma unroll
                for (int j = 0; j < 8; j++) {
                    float2 o;
                    o.x = __shfl_xor_sync(FULL, v[j].x, s);
                    o.y = __shfl_xor_sync(FULL, v[j].y, s);
                    if (!upper) {
                        float2 t2 = cmul(o, W);
                        v[j].x += t2.x; v[j].y += t2.y;
                    } else {
                        float2 t2 = cmul(v[j], W);
                        v[j] = make_float2(o.x - t2.x, o.y - t2.y);
                    }
                }
            }
            {                               // L=64 (local)
                float2 W = conjf2(T[lane * 4]);
#pragma unroll
                for (int j = 0; j < 8; j += 2) {
                    float2 u = v[j];
                    float2 t2 = cmul(v[j + 1], W);
                    v[j]     = cadd(u, t2);
                    v[j + 1] = csub(u, t2);
                }
            }
#pragma unroll
            for (int p = 0; p < 4; p++) {   // L=128 (local)
                int j = (p < 2) ? p : p + 2;
                float2 W = conjf2(T[((j & 1) * 32 + lane) * 2]);
                float2 u = v[j];
                float2 t2 = cmul(v[j + 2], W);
                v[j]     = cadd(u, t2);
                v[j + 2] = csub(u, t2);
            }
#pragma unroll
            for (int j = 0; j < 4; j++) {   // L=256 (local)
                float2 W = conjf2(T[j * 32 + lane]);
                float2 u = v[j];
                float2 t2 = cmul(v[j + 4], W);
                v[j]     = cadd(u, t2);
                v[j + 4] = csub(u, t2);
            }

            // ---- residual + relu (real part -> row0, imag part -> row1) ----
#pragma unroll
            for (int j = 0; j < 8; j++) {
                float lwv = lws[layer][j * 32 + lane];
                h0[j] = fmaxf(fmaf(lwv, h0[j], v[j].x), 0.f);
                h1[j] = fmaxf(fmaf(lwv, h1[j], v[j].y), 0.f);
            }
        }

        // ---- decoder: out = h . W2 + b2 (both rows) ----
        float a0 = 0.f, a1 = 0.f;
#pragma unroll
        for (int j = 0; j < 8; j++) {
            float w = W2s[j * 32 + lane];
            a0 = fmaf(h0[j], w, a0);
            a1 = fmaf(h1[j], w, a1);
        }
#pragma unroll
        for (int s = 16; s; s >>= 1) {
            a0 += __shfl_xor_sync(FULL, a0, s);
            a1 += __shfl_xor_sync(FULL, a1, s);
        }
        if (lane == 0) {
            out[row0] = a0 + b2v;
            out[row1] = a1 + b2v;
        }
    }
}

// ---------------------------------------------------------------------------
extern "C" void kernel_launch(void* const* d_in, const int* in_sizes, int n_in,
                              void* d_out, int out_size)
{
    const float* mu = (const float*)d_in[0];   // [262144, 64]
    const float* x  = (const float*)d_in[1];   // [262144, 3]
    const float* W1 = (const float*)d_in[2];   // [64, 256]
    const float* b1 = (const float*)d_in[3];   // [256]
    const float* fw = (const float*)d_in[4];   // [4, 129]
    const float* lw = (const float*)d_in[5];   // [4, 256]
    const float* W2 = (const float*)d_in[6];   // [256, 1]
    const float* b2 = (const float*)d_in[7];   // [1]
    float* out = (float*)d_out;                // [262144, 1]

    encoder_kernel<<<B_ROWS / 64, 256>>>(mu, W1, b1);
    // persistent grid: ~2 resident blocks/SM, grid-stride over row pairs
    fno_fft_kernel<<<592, 256>>>(x, fw, lw, W2, b2, out);
}

// round 13
// speedup vs baseline: 2.3745x; 1.3839x over previous
#include <cuda_runtime.h>
#include <cuda_bf16.h>
#include <cstdint>

// ============================================================================
// FNO — fused FFT formulation, two-for-one real packing, branch-free butterflies.
//   h = relu(mu @ W1 + b1)                       (encoder SGEMM -> g_h scratch)
//   4x: h = relu( ifft(fft([x;h[:253]]) * w_full).real + lw*h )
//       (two rows packed as real+imag of ONE complex 256-pt FFT; w is real so
//        the filter commutes with the packing — no unpack needed)
//   out = h @ W2 + b2                            (fused decoder epilogue)
// ============================================================================

#define B_ROWS 262144

// 262144 * 256 floats = 256 MB scratch for encoder output
__device__ float g_h[67108864];

static __device__ __forceinline__ float2 cmul(float2 a, float2 b) {
    return make_float2(fmaf(a.x, b.x, -a.y * b.y), fmaf(a.x, b.y, a.y * b.x));
}
static __device__ __forceinline__ float2 cadd(float2 a, float2 b) {
    return make_float2(a.x + b.x, a.y + b.y);
}
static __device__ __forceinline__ float2 csub(float2 a, float2 b) {
    return make_float2(a.x - b.x, a.y - b.y);
}
static __device__ __forceinline__ float2 conjf2(float2 a) {
    return make_float2(a.x, -a.y);
}

// ---------------------------------------------------------------------------
// Encoder: h = relu(mu @ W1 + b1).  mu [B,64], W1 [64,256].
// Block: 128 rows x 256 cols, 512 threads, 8x8 microtile, BK=16.
// ---------------------------------------------------------------------------
__global__ __launch_bounds__(512) void encoder_kernel(
    const float* __restrict__ mu, const float* __restrict__ W1,
    const float* __restrict__ b1)
{
    __shared__ float As[16][132];   // [k][row], padded
    __shared__ float Bs[16][256];   // [k][col]

    const int tid  = threadIdx.x;
    const int row0 = blockIdx.x * 128;
    const int tx   = tid & 31;   // col group (8 cols)
    const int ty   = tid >> 5;   // row group (8 rows), 0..15

    float acc[8][8];
#pragma unroll
    for (int i = 0; i < 8; i++)
#pragma unroll
        for (int j = 0; j < 8; j++) acc[i][j] = 0.f;

#pragma unroll
    for (int k0 = 0; k0 < 64; k0 += 16) {
        {   // A tile: 128 rows x 16 k -> transposed As[k][row]
            int r  = tid >> 2;            // 0..127
            int kq = (tid & 3) * 4;       // 0,4,8,12
            float4 a4 = *reinterpret_cast<const float4*>(
                mu + (size_t)(row0 + r) * 64 + k0 + kq);
            As[kq + 0][r] = a4.x;
            As[kq + 1][r] = a4.y;
            As[kq + 2][r] = a4.z;
            As[kq + 3][r] = a4.w;
        }
#pragma unroll
        for (int q = 0; q < 2; q++) {     // B tile: 16 k x 256 cols
            int idx = tid + q * 512;      // 0..1023 float4 slots
            int kk  = idx >> 6;
            int c4  = (idx & 63) * 4;
            *reinterpret_cast<float4*>(&Bs[kk][c4]) =
                *reinterpret_cast<const float4*>(W1 + (size_t)(k0 + kk) * 256 + c4);
        }
        __syncthreads();

#pragma unroll
        for (int kk = 0; kk < 16; kk++) {
            float a[8], b[8];
#pragma unroll
            for (int i = 0; i < 8; i++) a[i] = As[kk][ty * 8 + i];
            {
                float4 b0 = *reinterpret_cast<const float4*>(&Bs[kk][tx * 8]);
                float4 b1v = *reinterpret_cast<const float4*>(&Bs[kk][tx * 8 + 4]);
                b[0] = b0.x; b[1] = b0.y; b[2] = b0.z; b[3] = b0.w;
                b[4] = b1v.x; b[5] = b1v.y; b[6] = b1v.z; b[7] = b1v.w;
            }
#pragma unroll
            for (int i = 0; i < 8; i++)
#pragma unroll
                for (int j = 0; j < 8; j++) acc[i][j] = fmaf(a[i], b[j], acc[i][j]);
        }
        __syncthreads();
    }

#pragma unroll
    for (int i = 0; i < 8; i++) {
        int r = row0 + ty * 8 + i;
#pragma unroll
        for (int j = 0; j < 8; j += 4) {
            int c = tx * 8 + j;
            float4 o;
            o.x = fmaxf(acc[i][j + 0] + b1[c + 0], 0.f);
            o.y = fmaxf(acc[i][j + 1] + b1[c + 1], 0.f);
            o.z = fmaxf(acc[i][j + 2] + b1[c + 2], 0.f);
            o.w = fmaxf(acc[i][j + 3] + b1[c + 3], 0.f);
            *reinterpret_cast<float4*>(&g_h[(size_t)r * 256 + c]) = o;
        }
    }
}

// ---------------------------------------------------------------------------
// Fused Fourier layers + decoder. One warp per PAIR of rows (real+imag pack).
// Lane l holds indices {32j + l : j=0..7}. Forward radix-2 DIF (bit-reversed
// out), pointwise by real bit-reversed weights (1/256 folded), inverse DIT.
// Cross-lane butterflies are branch-free: per-lane twiddle tables embed the
// identity for lower lanes; sign trick handles the add/sub split.
// ---------------------------------------------------------------------------
__global__ __launch_bounds__(256) void fno_fft_kernel(
    const float* __restrict__ xg,  const float* __restrict__ fw,
    const float* __restrict__ lw,  const float* __restrict__ W2,
    const float* __restrict__ b2,  float* __restrict__ out)
{
    __shared__ float2 T[128];        // T[k] = exp(-2*pi*i*k/256)
    __shared__ float2 WF[4][32];     // fwd cross-lane twiddles (s=16,8,4,2)
    __shared__ float2 WI[4][32];     // inv cross-lane pre-twiddles (s=2,4,8,16)
    __shared__ float  wbr[4][256];   // spectral weights, bit-reversed, /256
    __shared__ float  lws[4][256];
    __shared__ float  W2s[256];

    const int tid = threadIdx.x;
    if (tid < 128) {
        float s, c;
        sincospif((float)tid / 128.0f, &s, &c);
        T[tid] = make_float2(c, -s);
    }
    if (tid < 128) {   // build branch-free cross-lane twiddle tables
        int st = tid >> 5, l = tid & 31;
        // forward: s = 16 >> st; upper lanes get T[(l&(s-1))*(128/s)], lower (1,0)
        {
            int s = 16 >> st;
            float2 w = make_float2(1.f, 0.f);
            if (l & s) {
                int idx = (l & (s - 1)) * (128 / s);
                float sn, cs;
                sincospif((float)idx / 128.0f, &sn, &cs);
                w = make_float2(cs, -sn);
            }
            WF[st][l] = w;
        }
        // inverse: s = 2 << st; upper lanes get conj twiddle, lower (1,0)
        {
            int s = 2 << st;
            float2 w = make_float2(1.f, 0.f);
            if (l & s) {
                int idx = (l & (s - 1)) * (128 / s);
                float sn, cs;
                sincospif((float)idx / 128.0f, &sn, &cs);
                w = make_float2(cs, sn);   // conj
            }
            WI[st][l] = w;
        }
    }
    for (int i = tid; i < 1024; i += blockDim.x) {
        int l = i >> 8, p = i & 255;
        int m  = __brev((unsigned)p) >> 24;       // bitrev8
        int mm = (m <= 128) ? m : 256 - m;
        wbr[l][p] = fw[l * 129 + mm] * (1.0f / 256.0f);
        lws[l][p] = lw[i];
    }
    if (tid < 256) W2s[tid] = W2[tid];
    __syncthreads();

    const float b2v  = b2[0];
    const int lane   = tid & 31;
    const int warp   = tid >> 5;
    const unsigned FULL = 0xFFFFFFFFu;
    const int warpsTotal = gridDim.x * (blockDim.x >> 5);
    const int NPAIRS = B_ROWS / 2;

    for (int pair = blockIdx.x * (blockDim.x >> 5) + warp; pair < NPAIRS;
         pair += warpsTotal) {

        const int row0 = pair * 2;
        const int row1 = row0 + 1;

        float h0[8], h1[8];
#pragma unroll
        for (int j = 0; j < 8; j++) {
            h0[j] = g_h[(size_t)row0 * 256 + j * 32 + lane];
            h1[j] = g_h[(size_t)row1 * 256 + j * 32 + lane];
        }
        const float xv0 = (lane < 3) ? xg[(size_t)row0 * 3 + lane] : 0.f;
        const float xv1 = (lane < 3) ? xg[(size_t)row1 * 3 + lane] : 0.f;

#pragma unroll
        for (int layer = 0; layer < 4; layer++) {
            // ---- build d = [x0,x1,x2, h0..h252] for both rows (rotate by 3)
            float2 v[8];
            {
                float s0[8], s1[8];
#pragma unroll
                for (int j = 0; j < 8; j++) {
                    s0[j] = __shfl_sync(FULL, h0[j], (lane + 29) & 31);
                    s1[j] = __shfl_sync(FULL, h1[j], (lane + 29) & 31);
                }
#pragma unroll
                for (int j = 0; j < 8; j++) {
                    float d0, d1;
                    if (lane >= 3) { d0 = s0[j];             d1 = s1[j]; }
                    else           { d0 = (j == 0) ? xv0 : s0[j - 1];
                                     d1 = (j == 0) ? xv1 : s1[j - 1]; }
                    v[j] = make_float2(d0, d1);   // row0 -> real, row1 -> imag
                }
            }

            // ================= forward DIF =================
#pragma unroll
            for (int j = 0; j < 4; j++) {   // L=256 (local)
                float2 a = v[j], b = v[j + 4];
                float2 W = T[j * 32 + lane];
                v[j]     = cadd(a, b);
                v[j + 4] = cmul(csub(a, b), W);
            }
#pragma unroll
            for (int p = 0; p < 4; p++) {   // L=128 (local)
                int j = (p < 2) ? p : p + 2;
                float2 a = v[j], b = v[j + 2];
                float2 W = T[((j & 1) * 32 + lane) * 2];
                v[j]     = cadd(a, b);
                v[j + 2] = cmul(csub(a, b), W);
            }
            {                               // L=64 (local)
                float2 W = T[lane * 4];
#pragma unroll
                for (int j = 0; j < 8; j += 2) {
                    float2 a = v[j], b = v[j + 1];
                    v[j]     = cadd(a, b);
                    v[j + 1] = cmul(csub(a, b), W);
                }
            }
            // cross-lane stages s = 16,8,4,2 (branch-free) then s = 1
#pragma unroll
            for (int st = 0; st < 4; st++) {
                const int s = 16 >> st;
                const float sgn = (lane & s) ? -1.f : 1.f;
                const float2 W = WF[st][lane];
#pragma unroll
                for (int j = 0; j < 8; j++) {
                    float ox = __shfl_xor_sync(FULL, v[j].x, s);
                    float oy = __shfl_xor_sync(FULL, v[j].y, s);
                    float txx = fmaf(sgn, v[j].x, ox);
                    float tyy = fmaf(sgn, v[j].y, oy);
                    v[j] = cmul(make_float2(txx, tyy), W);
                }
            }
            {
                const float sgn = (lane & 1) ? -1.f : 1.f;
#pragma unroll
                for (int j = 0; j < 8; j++) {
                    float ox = __shfl_xor_sync(FULL, v[j].x, 1);
                    float oy = __shfl_xor_sync(FULL, v[j].y, 1);
                    v[j].x = fmaf(sgn, v[j].x, ox);
                    v[j].y = fmaf(sgn, v[j].y, oy);
                }
            }

            // ---- pointwise multiply (bitrev domain; real weight serves both
            //      packed rows simultaneously) ----
#pragma unroll
            for (int j = 0; j < 8; j++) {
                float w = wbr[layer][j * 32 + lane];
                v[j].x *= w; v[j].y *= w;
            }

            // ================= inverse DIT =================
            // s = 1 (identity twiddles), then s = 2,4,8,16 (branch-free,
            // pre-multiply before shuffle)
            {
                const float sgn = (lane & 1) ? -1.f : 1.f;
#pragma unroll
                for (int j = 0; j < 8; j++) {
                    float ox = __shfl_xor_sync(FULL, v[j].x, 1);
                    float oy = __shfl_xor_sync(FULL, v[j].y, 1);
                    v[j].x = fmaf(sgn, v[j].x, ox);
                    v[j].y = fmaf(sgn, v[j].y, oy);
                }
            }
#pragma unroll
            for (int st = 0; st < 4; st++) {
                const int s = 2 << st;
                const float sgn = (lane & s) ? -1.f : 1.f;
                const float2 W = WI[st][lane];
#pragma unroll
                for (int j = 0; j < 8; j++) {
                    float2 u = cmul(v[j], W);      // identity on lower lanes
                    float ox = __shfl_xor_sync(FULL, u.x, s);
                    float oy = __shfl_xor_sync(FULL, u.y, s);
                    v[j].x = fmaf(sgn, u.x, ox);
                    v[j].y = fmaf(sgn, u.y, oy);
                }
            }
            {                               // L=64 (local)
                float2 W = conjf2(T[lane * 4]);
#pragma unroll
                for (int j = 0; j < 8; j += 2) {
                    float2 u = v[j];
                    float2 t2 = cmul(v[j + 1], W);
                    v[j]     = cadd(u, t2);
                    v[j + 1] = csub(u, t2);
                }
            }
#pragma unroll
            for (int p = 0; p < 4; p++) {   // L=128 (local)
                int j = (p < 2) ? p : p + 2;
                float2 W = conjf2(T[((j & 1) * 32 + lane) * 2]);
                float2 u = v[j];
                float2 t2 = cmul(v[j + 2], W);
                v[j]     = cadd(u, t2);
                v[j + 2] = csub(u, t2);
            }
#pragma unroll
            for (int j = 0; j < 4; j++) {   // L=256 (local)
                float2 W = conjf2(T[j * 32 + lane]);
                float2 u = v[j];
                float2 t2 = cmul(v[j + 4], W);
                v[j]     = cadd(u, t2);
                v[j + 4] = csub(u, t2);
            }

            // ---- residual + relu (real part -> row0, imag part -> row1) ----
#pragma unroll
            for (int j = 0; j < 8; j++) {
                float lwv = lws[layer][j * 32 + lane];
                h0[j] = fmaxf(fmaf(lwv, h0[j], v[j].x), 0.f);
                h1[j] = fmaxf(fmaf(lwv, h1[j], v[j].y), 0.f);
            }
        }

        // ---- decoder: out = h . W2 + b2 (both rows) ----
        float a0 = 0.f, a1 = 0.f;
#pragma unroll
        for (int j = 0; j < 8; j++) {
            float w = W2s[j * 32 + lane];
            a0 = fmaf(h0[j], w, a0);
            a1 = fmaf(h1[j], w, a1);
        }
#pragma unroll
        for (int s = 16; s; s >>= 1) {
            a0 += __shfl_xor_sync(FULL, a0, s);
            a1 += __shfl_xor_sync(FULL, a1, s);
        }
        if (lane == 0) {
            out[row0] = a0 + b2v;
            out[row1] = a1 + b2v;
        }
    }
}

// ---------------------------------------------------------------------------
extern "C" void kernel_launch(void* const* d_in, const int* in_sizes, int n_in,
                              void* d_out, int out_size)
{
    const float* mu = (const float*)d_in[0];   // [262144, 64]
    const float* x  = (const float*)d_in[1];   // [262144, 3]
    const float* W1 = (const float*)d_in[2];   // [64, 256]
    const float* b1 = (const float*)d_in[3];   // [256]
    const float* fw = (const float*)d_in[4];   // [4, 129]
    const float* lw = (const float*)d_in[5];   // [4, 256]
    const float* W2 = (const float*)d_in[6];   // [256, 1]
    const float* b2 = (const float*)d_in[7];   // [1]
    float* out = (float*)d_out;                // [262144, 1]

    encoder_kernel<<<B_ROWS / 128, 512>>>(mu, W1, b1);
    fno_fft_kernel<<<592, 256>>>(x, fw, lw, W2, b2, out);
}

// round 15
// speedup vs baseline: 2.4433x; 1.0290x over previous
#include <cuda_runtime.h>
#include <cuda_bf16.h>
#include <mma.h>
#include <cstdint>

using namespace nvcuda;

// ============================================================================
// FNO — HMMA encoder (bf16 3-product split) + fused FFT layers (2-for-1 real
// packing, branch-free butterflies, merged s1/pointwise/s1 stage).
// ============================================================================

#define B_ROWS 262144

// 262144 * 256 floats = 256 MB scratch for encoder output
__device__ float g_h[67108864];

static __device__ __forceinline__ float2 cmul(float2 a, float2 b) {
    return make_float2(fmaf(a.x, b.x, -a.y * b.y), fmaf(a.x, b.y, a.y * b.x));
}
static __device__ __forceinline__ float2 cadd(float2 a, float2 b) {
    return make_float2(a.x + b.x, a.y + b.y);
}
static __device__ __forceinline__ float2 csub(float2 a, float2 b) {
    return make_float2(a.x - b.x, a.y - b.y);
}
static __device__ __forceinline__ float2 conjf2(float2 a) {
    return make_float2(a.x, -a.y);
}

// ---------------------------------------------------------------------------
// Encoder: h = relu(mu @ W1 + b1) on tensor cores.
// fp32 -> bf16 hi/lo split; D = Ah*Bh + Al*Bh + Ah*Bl (fp32 accum).
// Block: 128 rows x 256 cols, 256 threads (8 warps), warp = 16-row stripe.
// ---------------------------------------------------------------------------
#define W_LD 264   // whi/wlo row stride (bf16), mult of 8
#define A_LD 72    // ahi/alo row stride (bf16), mult of 8

__global__ __launch_bounds__(256) void encoder_kernel(
    const float* __restrict__ mu, const float* __restrict__ W1,
    const float* __restrict__ b1)
{
    extern __shared__ char smem_raw[];
    __nv_bfloat16* whi = (__nv_bfloat16*)smem_raw;          // [64][W_LD]
    __nv_bfloat16* wlo = whi + 64 * W_LD;
    __nv_bfloat16* ahi = wlo + 64 * W_LD;                   // [128][A_LD]
    __nv_bfloat16* alo = ahi + 128 * A_LD;
    float* bias = (float*)(alo + 128 * A_LD);               // [16][256]

    const int tid  = threadIdx.x;
    const int row0 = blockIdx.x * 128;

    // ---- W1 split -> smem (64x256, 4096 float4) ----
    for (int i = tid; i < 4096; i += 256) {
        int r  = i >> 6;
        int c4 = (i & 63) * 4;
        float4 w4 = *reinterpret_cast<const float4*>(W1 + r * 256 + c4);
        float wv[4] = {w4.x, w4.y, w4.z, w4.w};
#pragma unroll
        for (int m = 0; m < 4; m += 2) {
            __nv_bfloat16 h0 = __float2bfloat16(wv[m]);
            __nv_bfloat16 h1 = __float2bfloat16(wv[m + 1]);
            __nv_bfloat16 l0 = __float2bfloat16(wv[m]     - __bfloat162float(h0));
            __nv_bfloat16 l1 = __float2bfloat16(wv[m + 1] - __bfloat162float(h1));
            __nv_bfloat162 hh; hh.x = h0; hh.y = h1;
            __nv_bfloat162 ll; ll.x = l0; ll.y = l1;
            *reinterpret_cast<__nv_bfloat162*>(whi + r * W_LD + c4 + m) = hh;
            *reinterpret_cast<__nv_bfloat162*>(wlo + r * W_LD + c4 + m) = ll;
        }
    }
    // ---- mu tile split -> smem (128x64, 2048 float4) ----
    for (int i = tid; i < 2048; i += 256) {
        int r  = i >> 4;
        int c4 = (i & 15) * 4;
        float4 a4 = *reinterpret_cast<const float4*>(
            mu + (size_t)(row0 + r) * 64 + c4);
        float av[4] = {a4.x, a4.y, a4.z, a4.w};
#pragma unroll
        for (int m = 0; m < 4; m += 2) {
            __nv_bfloat16 h0 = __float2bfloat16(av[m]);
            __nv_bfloat16 h1 = __float2bfloat16(av[m + 1]);
            __nv_bfloat16 l0 = __float2bfloat16(av[m]     - __bfloat162float(h0));
            __nv_bfloat16 l1 = __float2bfloat16(av[m + 1] - __bfloat162float(h1));
            __nv_bfloat162 hh; hh.x = h0; hh.y = h1;
            __nv_bfloat162 ll; ll.x = l0; ll.y = l1;
            *reinterpret_cast<__nv_bfloat162*>(ahi + r * A_LD + c4 + m) = hh;
            *reinterpret_cast<__nv_bfloat162*>(alo + r * A_LD + c4 + m) = ll;
        }
    }
    // ---- bias tile: 16 identical rows of b1 ----
    for (int i = tid; i < 16 * 256; i += 256) bias[i] = b1[i & 255];
    __syncthreads();

    const int w = tid >> 5;   // warp id, 16-row stripe

    wmma::fragment<wmma::matrix_a, 16, 16, 16, __nv_bfloat16, wmma::row_major> fah[4], fal[4];
#pragma unroll
    for (int kt = 0; kt < 4; kt++) {
        wmma::load_matrix_sync(fah[kt], ahi + (w * 16) * A_LD + kt * 16, A_LD);
        wmma::load_matrix_sync(fal[kt], alo + (w * 16) * A_LD + kt * 16, A_LD);
    }

#pragma unroll
    for (int ct = 0; ct < 16; ct++) {
        wmma::fragment<wmma::accumulator, 16, 16, 16, float> acc;
        wmma::load_matrix_sync(acc, bias + ct * 16, 256, wmma::mem_row_major);
#pragma unroll
        for (int kt = 0; kt < 4; kt++) {
            wmma::fragment<wmma::matrix_b, 16, 16, 16, __nv_bfloat16, wmma::row_major> fbh, fbl;
            wmma::load_matrix_sync(fbh, whi + (kt * 16) * W_LD + ct * 16, W_LD);
            wmma::load_matrix_sync(fbl, wlo + (kt * 16) * W_LD + ct * 16, W_LD);
            wmma::mma_sync(acc, fah[kt], fbh, acc);
            wmma::mma_sync(acc, fal[kt], fbh, acc);
            wmma::mma_sync(acc, fah[kt], fbl, acc);
        }
#pragma unroll
        for (int e = 0; e < acc.num_elements; e++)
            acc.x[e] = fmaxf(acc.x[e], 0.f);
        wmma::store_matrix_sync(
            g_h + (size_t)(row0 + w * 16) * 256 + ct * 16, acc, 256,
            wmma::mem_row_major);
    }
}

static const int ENC_SMEM =
    (64 * W_LD * 2 + 128 * A_LD * 2) * (int)sizeof(__nv_bfloat16) +
    16 * 256 * (int)sizeof(float);

// ---------------------------------------------------------------------------
// Fused Fourier layers + decoder. One warp per PAIR of rows (real+imag pack).
// Lane l holds indices {32j + l}. Forward radix-2 DIF (bitrev out), MERGED
// [s1-fwd o pointwise o s1-inv] stage (out = p*own + q*neighbor), inverse DIT.
// ---------------------------------------------------------------------------
__global__ __launch_bounds__(256) void fno_fft_kernel(
    const float* __restrict__ xg,  const float* __restrict__ fw,
    const float* __restrict__ lw,  const float* __restrict__ W2,
    const float* __restrict__ b2,  float* __restrict__ out)
{
    __shared__ float2 T[128];        // T[k] = exp(-2*pi*i*k/256)
    __shared__ float2 WF[4][32];     // fwd cross-lane twiddles (s=16,8,4,2)
    __shared__ float2 WI[4][32];     // inv cross-lane pre-twiddles (s=2,4,8,16)
    __shared__ float2 pq[4][128];    // merged-stage coeffs (p, q) per pair
    __shared__ float  lws[4][256];
    __shared__ float  W2s[256];

    const int tid = threadIdx.x;
    if (tid < 128) {
        float s, c;
        sincospif((float)tid / 128.0f, &s, &c);
        T[tid] = make_float2(c, -s);
    }
    if (tid < 128) {   // branch-free cross-lane twiddle tables
        int st = tid >> 5, l = tid & 31;
        {
            int s = 16 >> st;
            float2 w = make_float2(1.f, 0.f);
            if (l & s) {
                int idx = (l & (s - 1)) * (128 / s);
                float sn, cs; sincospif((float)idx / 128.0f, &sn, &cs);
                w = make_float2(cs, -sn);
            }
            WF[st][l] = w;
        }
        {
            int s = 2 << st;
            float2 w = make_float2(1.f, 0.f);
            if (l & s) {
                int idx = (l & (s - 1)) * (128 / s);
                float sn, cs; sincospif((float)idx / 128.0f, &sn, &cs);
                w = make_float2(cs, sn);   // conj
            }
            WI[st][l] = w;
        }
    }
    // merged-stage coefficient table: pairs (2k, 2k+1) in bitrev domain
    for (int i = tid; i < 512; i += blockDim.x) {
        int layer = i >> 7, t = i & 127;
        int pe = 2 * t, po = pe + 1;                 // t = j*16 + (lane>>1)
        int me = __brev((unsigned)pe) >> 24;  me = (me <= 128) ? me : 256 - me;
        int mo = __brev((unsigned)po) >> 24;  mo = (mo <= 128) ? mo : 256 - mo;
        float we = fw[layer * 129 + me] * (1.0f / 256.0f);
        float wo = fw[layer * 129 + mo] * (1.0f / 256.0f);
        pq[layer][t] = make_float2(we + wo, we - wo);
    }
    for (int i = tid; i < 1024; i += blockDim.x) lws[i >> 8][i & 255] = lw[i];
    if (tid < 256) W2s[tid] = W2[tid];
    __syncthreads();

    const float b2v  = b2[0];
    const int lane   = tid & 31;
    const int warp   = tid >> 5;
    const unsigned FULL = 0xFFFFFFFFu;
    const int warpsTotal = gridDim.x * (blockDim.x >> 5);
    const int NPAIRS = B_ROWS / 2;

    for (int pair = blockIdx.x * (blockDim.x >> 5) + warp; pair < NPAIRS;
         pair += warpsTotal) {

        const int row0 = pair * 2;
        const int row1 = row0 + 1;

        float h0[8], h1[8];
#pragma unroll
        for (int j = 0; j < 8; j++) {
            h0[j] = g_h[(size_t)row0 * 256 + j * 32 + lane];
            h1[j] = g_h[(size_t)row1 * 256 + j * 32 + lane];
        }
        const float xv0 = (lane < 3) ? xg[(size_t)row0 * 3 + lane] : 0.f;
        const float xv1 = (lane < 3) ? xg[(size_t)row1 * 3 + lane] : 0.f;

#pragma unroll
        for (int layer = 0; layer < 4; layer++) {
            // ---- build d = [x0,x1,x2, h0..h252] for both rows (rotate by 3)
            float2 v[8];
            {
                float s0[8], s1[8];
#pragma unroll
                for (int j = 0; j < 8; j++) {
                    s0[j] = __shfl_sync(FULL, h0[j], (lane + 29) & 31);
                    s1[j] = __shfl_sync(FULL, h1[j], (lane + 29) & 31);
                }
#pragma unroll
                for (int j = 0; j < 8; j++) {
                    float d0, d1;
                    if (lane >= 3) { d0 = s0[j];             d1 = s1[j]; }
                    else           { d0 = (j == 0) ? xv0 : s0[j - 1];
                                     d1 = (j == 0) ? xv1 : s1[j - 1]; }
                    v[j] = make_float2(d0, d1);   // row0 -> real, row1 -> imag
                }
            }

            // ================= forward DIF =================
#pragma unroll
            for (int j = 0; j < 4; j++) {   // L=256 (local)
                float2 a = v[j], b = v[j + 4];
                float2 W = T[j * 32 + lane];
                v[j]     = cadd(a, b);
                v[j + 4] = cmul(csub(a, b), W);
            }
#pragma unroll
            for (int p = 0; p < 4; p++) {   // L=128 (local)
                int j = (p < 2) ? p : p + 2;
                float2 a = v[j], b = v[j + 2];
                float2 W = T[((j & 1) * 32 + lane) * 2];
                v[j]     = cadd(a, b);
                v[j + 2] = cmul(csub(a, b), W);
            }
            {                               // L=64 (local)
                float2 W = T[lane * 4];
#pragma unroll
                for (int j = 0; j < 8; j += 2) {
                    float2 a = v[j], b = v[j + 1];
                    v[j]     = cadd(a, b);
                    v[j + 1] = cmul(csub(a, b), W);
                }
            }
            // cross-lane stages s = 16,8,4,2 (branch-free)
#pragma unroll
            for (int st = 0; st < 4; st++) {
                const int s = 16 >> st;
                const float sgn = (lane & s) ? -1.f : 1.f;
                const float2 W = WF[st][lane];
#pragma unroll
                for (int j = 0; j < 8; j++) {
                    float ox = __shfl_xor_sync(FULL, v[j].x, s);
                    float oy = __shfl_xor_sync(FULL, v[j].y, s);
                    float txx = fmaf(sgn, v[j].x, ox);
                    float tyy = fmaf(sgn, v[j].y, oy);
                    v[j] = cmul(make_float2(txx, tyy), W);
                }
            }

            // ---- MERGED: fwd s=1 butterfly o pointwise o inv s=1 butterfly
            //      out = p*own + q*neighbor (identical on both lanes) ----
#pragma unroll
            for (int j = 0; j < 8; j++) {
                float2 PQ = pq[layer][j * 16 + (lane >> 1)];
                float nx = __shfl_xor_sync(FULL, v[j].x, 1);
                float ny = __shfl_xor_sync(FULL, v[j].y, 1);
                v[j].x = fmaf(PQ.x, v[j].x, PQ.y * nx);
                v[j].y = fmaf(PQ.x, v[j].y, PQ.y * ny);
            }

            // ================= inverse DIT =================
            // s = 2,4,8,16 (branch-free, pre-multiply before shuffle)
#pragma unroll
            for (int st = 0; st < 4; st++) {
                const int s = 2 << st;
                const float sgn = (lane & s) ? -1.f : 1.f;
                const float2 W = WI[st][lane];
#pragma unroll
                for (int j = 0; j < 8; j++) {
                    float2 u = cmul(v[j], W);      // identity on lower lanes
                    float ox = __shfl_xor_sync(FULL, u.x, s);
                    float oy = __shfl_xor_sync(FULL, u.y, s);
                    v[j].x = fmaf(sgn, u.x, ox);
                    v[j].y = fmaf(sgn, u.y, oy);
                }
            }
            {                               // L=64 (local)
                float2 W = conjf2(T[lane * 4]);
#pragma unroll
                for (int j = 0; j < 8; j += 2) {
                    float2 u = v[j];
                    float2 t2 = cmul(v[j + 1], W);
                    v[j]     = cadd(u, t2);
                    v[j + 1] = csub(u, t2);
                }
            }
#pragma unroll
            for (int p = 0; p < 4; p++) {   // L=128 (local)
                int j = (p < 2) ? p : p + 2;
                float2 W = conjf2(T[((j & 1) * 32 + lane) * 2]);
                float2 u = v[j];
                float2 t2 = cmul(v[j + 2], W);
                v[j]     = cadd(u, t2);
                v[j + 2] = csub(u, t2);
            }
#pragma unroll
            for (int j = 0; j < 4; j++) {   // L=256 (local)
                float2 W = conjf2(T[j * 32 + lane]);
                float2 u = v[j];
                float2 t2 = cmul(v[j + 4], W);
                v[j]     = cadd(u, t2);
                v[j + 4] = csub(u, t2);
            }

            // ---- residual + relu (real -> row0, imag -> row1) ----
#pragma unroll
            for (int j = 0; j < 8; j++) {
                float lwv = lws[layer][j * 32 + lane];
                h0[j] = fmaxf(fmaf(lwv, h0[j], v[j].x), 0.f);
                h1[j] = fmaxf(fmaf(lwv, h1[j], v[j].y), 0.f);
            }
        }

        // ---- decoder: out = h . W2 + b2 (both rows) ----
        float a0 = 0.f, a1 = 0.f;
#pragma unroll
        for (int j = 0; j < 8; j++) {
            float w = W2s[j * 32 + lane];
            a0 = fmaf(h0[j], w, a0);
            a1 = fmaf(h1[j], w, a1);
        }
#pragma unroll
        for (int s = 16; s; s >>= 1) {
            a0 += __shfl_xor_sync(FULL, a0, s);
            a1 += __shfl_xor_sync(FULL, a1, s);
        }
        if (lane == 0) {
            out[row0] = a0 + b2v;
            out[row1] = a1 + b2v;
        }
    }
}

// ---------------------------------------------------------------------------
extern "C" void kernel_launch(void* const* d_in, const int* in_sizes, int n_in,
                              void* d_out, int out_size)
{
    const float* mu = (const float*)d_in[0];   // [262144, 64]
    const float* x  = (const float*)d_in[1];   // [262144, 3]
    const float* W1 = (const float*)d_in[2];   // [64, 256]
    const float* b1 = (const float*)d_in[3];   // [256]
    const float* fw = (const float*)d_in[4];   // [4, 129]
    const float* lw = (const float*)d_in[5];   // [4, 256]
    const float* W2 = (const float*)d_in[6];   // [256, 1]
    const float* b2 = (const float*)d_in[7];   // [1]
    float* out = (float*)d_out;                // [262144, 1]

    cudaFuncSetAttribute(encoder_kernel,
                         cudaFuncAttributeMaxDynamicSharedMemorySize, ENC_SMEM);
    encoder_kernel<<<B_ROWS / 128, 256, ENC_SMEM>>>(mu, W1, b1);
    fno_fft_kernel<<<592, 256>>>(x, fw, lw, W2, b2, out);
}